// round 1
// baseline (speedup 1.0000x reference)
#include <cuda_runtime.h>
#include <math.h>

#define NB 32
#define NA 3
#define NH 52
#define NW 52
#define NG 50
#define NC 80
#define HW (NH * NW)
#define CELLS (NB * NA * HW)   // 259584
#define NTGT (NB * NG)         // 1600

// Scratch (allocation-free rule: __device__ globals)
__device__ int            g_winner[CELLS];
__device__ unsigned char  g_noobj[CELLS];
__device__ double         g_acc[8];
// acc: 0=sum_x 1=sum_y 2=sum_w 3=sum_h 4=sum_conf_obj 5=sum_noobj 6=sum_cls 7=npos

__device__ __forceinline__ float clog(float x) {
    // torch BCELoss-style clamp: log lower-bounded at -100
    return fmaxf(logf(x), -100.0f);
}
__device__ __forceinline__ float bce(float p, float t) {
    return -(t * clog(p) + (1.0f - t) * clog(1.0f - p));
}
__device__ __forceinline__ float sigm(float x) {
    return 1.0f / (1.0f + expf(-x));
}

__global__ void k_init() {
    int i = blockIdx.x * blockDim.x + threadIdx.x;
    if (i < CELLS) { g_winner[i] = -1; g_noobj[i] = 1; }
    if (i < 8) g_acc[i] = 0.0;
}

__global__ void k_targets(const float* __restrict__ tg) {
    int g = blockIdx.x * blockDim.x + threadIdx.x;
    if (g >= NTGT) return;
    int b = g / NG;
    const float* t = tg + (size_t)g * 5;
    // scaled anchors: ANCHORS / (416/52) = ANCHORS / 8
    const float aw[3] = {1.25f, 2.0f, 4.125f};
    const float ah[3] = {1.625f, 3.75f, 2.875f};
    float gx = t[1] * ((float)NW / 416.0f);
    float gy = t[2] * ((float)NH / 416.0f);
    float gw = t[3] * ((float)NW / 416.0f);
    float gh = t[4] * ((float)NH / 416.0f);
    int gi = min(max((int)gx, 0), NW - 1);
    int gj = min(max((int)gy, 0), NH - 1);
    float area_g = (gw + 1.0f) * (gh + 1.0f);
    float best_iou = -1.0f;
    int best = 0;
#pragma unroll
    for (int a = 0; a < 3; a++) {
        float iw = fmaxf(fminf(gw, aw[a]) + 1.0f, 0.0f);
        float ih = fmaxf(fminf(gh, ah[a]) + 1.0f, 0.0f);
        float inter = iw * ih;
        float area_a = (aw[a] + 1.0f) * (ah[a] + 1.0f);
        float iou = inter / (area_g + area_a - inter + 1e-16f);
        if (iou > best_iou) { best_iou = iou; best = a; }   // first-max tie = jnp.argmax
        if (iou > 0.5f) g_noobj[((b * NA + a) * NH + gj) * NW + gi] = 0;
    }
    g_winner[((b * NA + best) * NH + gj) * NW + gi] = g;     // coherent last-writer-wins
}

__global__ void k_main(const float* __restrict__ in, const float* __restrict__ tg) {
    int idx = blockIdx.x * blockDim.x + threadIdx.x;
    float sx = 0.f, sy = 0.f, sw = 0.f, sh = 0.f;
    float sconf = 0.f, snoobj = 0.f, scls = 0.f, snp = 0.f;
    if (idx < CELLS) {
        int w = idx % NW;
        int h = (idx / NW) % NH;
        int a = (idx / HW) % NA;
        int b = idx / (NA * HW);
        const float* base = in + ((size_t)(b * 255 + a * 85)) * HW + (size_t)h * NW + w;
        float pconf = sigm(base[4 * HW]);
        if (g_noobj[idx]) snoobj = -clog(1.0f - pconf);      // bce(p, 0)
        int win = g_winner[idx];
        if (win >= 0) {
            const float aw[3] = {1.25f, 2.0f, 4.125f};
            const float ah[3] = {1.625f, 3.75f, 2.875f};
            const float* t = tg + (size_t)win * 5;
            float gx = t[1] * ((float)NW / 416.0f);
            float gy = t[2] * ((float)NH / 416.0f);
            float gw = t[3] * ((float)NW / 416.0f);
            float gh = t[4] * ((float)NH / 416.0f);
            float tx = gx - (float)w;                        // w == gi by construction
            float ty = gy - (float)h;                        // h == gj
            float tw = logf(gw / aw[a] + 1e-16f);
            float th = logf(gh / ah[a] + 1e-16f);
            int clsid = min(max((int)t[0], 0), NC - 1);
            sx = bce(sigm(base[0]), tx);
            sy = bce(sigm(base[HW]), ty);
            float dw = base[2 * HW] - tw;  sw = dw * dw;
            float dh = base[3 * HW] - th;  sh = dh * dh;
            sconf = -clog(pconf);                            // bce(p, 1)
#pragma unroll 8
            for (int c = 0; c < NC; c++) {
                float pc = sigm(base[(5 + c) * HW]);
                scls += bce(pc, (c == clsid) ? 1.0f : 0.0f);
            }
            snp = 1.0f;
        }
    }
    // block reduction: warp shuffle -> shared -> 8 double atomics per block
    float vals[8] = {sx, sy, sw, sh, sconf, snoobj, scls, snp};
    __shared__ float sacc[8];
    if (threadIdx.x < 8) sacc[threadIdx.x] = 0.0f;
    __syncthreads();
    unsigned lane = threadIdx.x & 31;
#pragma unroll
    for (int k = 0; k < 8; k++) {
        float v = vals[k];
#pragma unroll
        for (int o = 16; o > 0; o >>= 1) v += __shfl_down_sync(0xffffffffu, v, o);
        if (lane == 0) atomicAdd(&sacc[k], v);
    }
    __syncthreads();
    if (threadIdx.x < 8) atomicAdd(&g_acc[threadIdx.x], (double)sacc[threadIdx.x]);
}

__global__ void k_final(float* __restrict__ out) {
    const double N = (double)CELLS;
    double lx = g_acc[0] / N;
    double ly = g_acc[1] / N;
    double lw = g_acc[2] / N;
    double lh = g_acc[3] / N;
    double lconf = g_acc[4] / N + 0.5 * (g_acc[5] / N);
    double denom = g_acc[7] * (double)NC;
    if (denom < 1.0) denom = 1.0;
    double lcls = g_acc[6] / denom;
    out[0] = (float)(2.5 * (lx + ly) + 2.5 * (lw + lh) + lconf + lcls);
}

extern "C" void kernel_launch(void* const* d_in, const int* in_sizes, int n_in,
                              void* d_out, int out_size) {
    const float* inp = (const float*)d_in[0];   // [32,255,52,52]
    const float* tgt = (const float*)d_in[1];   // [32,50,5]
    float* out = (float*)d_out;

    const int threads = 256;
    const int blocksCells = (CELLS + threads - 1) / threads;   // 1015
    const int blocksTgt = (NTGT + threads - 1) / threads;      // 7

    k_init<<<blocksCells, threads>>>();
    k_targets<<<blocksTgt, threads>>>(tgt);
    k_main<<<blocksCells, threads>>>(inp, tgt);
    k_final<<<1, 1>>>(out);
}

// round 2
// speedup vs baseline: 1.0054x; 1.0054x over previous
#include <cuda_runtime.h>
#include <math.h>

#define NB 32
#define NA 3
#define NH 52
#define NW 52
#define NG 50
#define NC 80
#define HW (NH * NW)            // 2704
#define TPB 256
#define BPS 11                  // blocks per (b,a) slice: 11*256 = 2816 >= 2704
#define GRID (NB * NA * BPS)    // 1056

// acc: 0=sum_x 1=sum_y 2=sum_w 3=sum_h 4=sum_conf_obj 5=sum_noobj 6=sum_cls 7=npos
__device__ double       g_acc[8];      // zero-init; epilogue restores zeros each call
__device__ unsigned int g_done;        // zero-init; epilogue restores zero

__device__ __forceinline__ float clog(float x) {
    return fmaxf(logf(x), -100.0f);    // torch BCELoss log clamp
}
__device__ __forceinline__ float bce(float p, float t) {
    return -(t * clog(p) + (1.0f - t) * clog(1.0f - p));
}
__device__ __forceinline__ float sigm(float x) {
    return 1.0f / (1.0f + expf(-x));
}

__constant__ float c_aw[3] = {1.25f, 2.0f, 4.125f};   // ANCHORS[:,0] / 8
__constant__ float c_ah[3] = {1.625f, 3.75f, 2.875f}; // ANCHORS[:,1] / 8

__global__ void __launch_bounds__(TPB)
k_fused(const float* __restrict__ in, const float* __restrict__ tg,
        float* __restrict__ out) {
    const int slice = blockIdx.x / BPS;       // 0..95 -> (b,a)
    const int pblk  = blockIdx.x % BPS;
    const int b = slice / NA;
    const int a = slice % NA;
    const int p0 = pblk * TPB;
    const int p  = p0 + threadIdx.x;          // cell within HxW slice

    __shared__ int           swin[TPB];       // winning target g, -1 = none
    __shared__ unsigned char ssup[TPB];       // 1 = suppress noobj term
    __shared__ float         sacc[8];
    __shared__ unsigned int  s_last;

    swin[threadIdx.x] = -1;
    ssup[threadIdx.x] = 0;
    if (threadIdx.x < 8) sacc[threadIdx.x] = 0.0f;
    __syncthreads();

    // ---- targets for this batch: threads 0..49, scatter into shared maps ----
    if (threadIdx.x < NG) {
        const int g = b * NG + threadIdx.x;
        const float* t = tg + (size_t)g * 5;
        float gx = t[1] * ((float)NW / 416.0f);
        float gy = t[2] * ((float)NH / 416.0f);
        float gw = t[3] * ((float)NW / 416.0f);
        float gh = t[4] * ((float)NH / 416.0f);
        int gi = min(max((int)gx, 0), NW - 1);
        int gj = min(max((int)gy, 0), NH - 1);
        int cell = gj * NW + gi;
        if (cell >= p0 && cell < p0 + TPB) {
            int local = cell - p0;
            float area_g = (gw + 1.0f) * (gh + 1.0f);
            float best_iou = -1.0f;
            int best = 0;
            float iou_a = 0.0f;
#pragma unroll
            for (int k = 0; k < 3; k++) {
                float iw = fmaxf(fminf(gw, c_aw[k]) + 1.0f, 0.0f);
                float ih = fmaxf(fminf(gh, c_ah[k]) + 1.0f, 0.0f);
                float inter = iw * ih;
                float area_k = (c_aw[k] + 1.0f) * (c_ah[k] + 1.0f);
                float iou = inter / (area_g + area_k - inter + 1e-16f);
                if (iou > best_iou) { best_iou = iou; best = k; }  // first-max = jnp.argmax
                if (k == a) iou_a = iou;
            }
            if (iou_a > 0.5f) ssup[local] = 1;            // order-free (all write 1)
            if (best == a) atomicMax(&swin[local], g);    // highest-g wins = last update
        }
    }
    __syncthreads();

    // ---- per-cell loss contributions ----
    float sx = 0.f, sy = 0.f, sw = 0.f, sh = 0.f;
    float sconf = 0.f, snoobj = 0.f, scls = 0.f, snp = 0.f;
    if (p < HW) {
        const int w = p % NW;
        const int h = p / NW;
        const float* base = in + ((size_t)(b * 255 + a * 85)) * HW + (size_t)h * NW + w;
        float pconf = sigm(base[4 * HW]);
        if (!ssup[threadIdx.x]) snoobj = -clog(1.0f - pconf);   // bce(conf, 0)
        int win = swin[threadIdx.x];
        if (win >= 0) {
            const float* t = tg + (size_t)win * 5;
            float gx = t[1] * ((float)NW / 416.0f);
            float gy = t[2] * ((float)NH / 416.0f);
            float gw = t[3] * ((float)NW / 416.0f);
            float gh = t[4] * ((float)NH / 416.0f);
            float tx = gx - (float)w;                     // w == gi for winner cell
            float ty = gy - (float)h;                     // h == gj
            float tw = logf(gw / c_aw[a] + 1e-16f);
            float th = logf(gh / c_ah[a] + 1e-16f);
            int clsid = min(max((int)t[0], 0), NC - 1);
            sx = bce(sigm(base[0]), tx);
            sy = bce(sigm(base[HW]), ty);
            float dw = base[2 * HW] - tw;  sw = dw * dw;
            float dh = base[3 * HW] - th;  sh = dh * dh;
            sconf = -clog(pconf);                         // bce(conf, 1)
#pragma unroll 8
            for (int c = 0; c < NC; c++) {
                float pc = sigm(base[(5 + c) * HW]);
                scls += bce(pc, (c == clsid) ? 1.0f : 0.0f);
            }
            snp = 1.0f;
        }
    }

    // ---- block reduction: warp shuffle -> shared -> global double atomics ----
    float vals[8] = {sx, sy, sw, sh, sconf, snoobj, scls, snp};
    unsigned lane = threadIdx.x & 31;
#pragma unroll
    for (int k = 0; k < 8; k++) {
        float v = vals[k];
#pragma unroll
        for (int o = 16; o > 0; o >>= 1) v += __shfl_down_sync(0xffffffffu, v, o);
        if (lane == 0) atomicAdd(&sacc[k], v);
    }
    __syncthreads();
    if (threadIdx.x < 8) atomicAdd(&g_acc[threadIdx.x], (double)sacc[threadIdx.x]);

    // ---- last block finalizes + resets state for next graph replay ----
    if (threadIdx.x == 0) {
        __threadfence();
        unsigned int v = atomicAdd(&g_done, 1u);
        s_last = (v == (unsigned int)(gridDim.x - 1)) ? 1u : 0u;
    }
    __syncthreads();
    if (s_last && threadIdx.x == 0) {
        const double N = (double)(NB * NA * HW);
        double lx = g_acc[0] / N;
        double ly = g_acc[1] / N;
        double lw = g_acc[2] / N;
        double lh = g_acc[3] / N;
        double lconf = g_acc[4] / N + 0.5 * (g_acc[5] / N);
        double denom = g_acc[7] * (double)NC;
        if (denom < 1.0) denom = 1.0;
        double lcls = g_acc[6] / denom;
        out[0] = (float)(2.5 * (lx + ly) + 2.5 * (lw + lh) + lconf + lcls);
#pragma unroll
        for (int k = 0; k < 8; k++) g_acc[k] = 0.0;       // restore pristine state
        g_done = 0u;
        __threadfence();
    }
}

extern "C" void kernel_launch(void* const* d_in, const int* in_sizes, int n_in,
                              void* d_out, int out_size) {
    const float* inp = (const float*)d_in[0];   // [32,255,52,52]
    const float* tgt = (const float*)d_in[1];   // [32,50,5]
    k_fused<<<GRID, TPB>>>(inp, tgt, (float*)d_out);
}

// round 3
// speedup vs baseline: 1.4178x; 1.4102x over previous
#include <cuda_runtime.h>
#include <math.h>

#define NB 32
#define NA 3
#define NH 52
#define NW 52
#define NG 50
#define NC 80
#define HW (NH * NW)            // 2704
#define F4C (HW / 4)            // 676 float4 per channel
#define TPB 256
#define CPB 1024                // cells per block window
#define BPS 3                   // blocks per (b,a) slice
#define GRID (NB * NA * BPS)    // 288
#define CELLS (NB * NA * HW)    // 259584

__device__ float        g_part[GRID * 8];   // per-block partials (overwritten each call)
__device__ unsigned int g_done;             // zero-init; last block restores zero

__constant__ float c_aw[3] = {1.25f, 2.0f, 4.125f};   // ANCHORS[:,0] / 8
__constant__ float c_ah[3] = {1.625f, 3.75f, 2.875f}; // ANCHORS[:,1] / 8

// min(softplus(x), 100): bce(sigm(x),0) with torch's log clamp at -100
__device__ __forceinline__ float sp(float x) {
    float r = fmaxf(x, 0.0f) + __logf(1.0f + __expf(-fabsf(x)));
    return fminf(r, 100.0f);
}

__global__ void __launch_bounds__(TPB)
k_fused(const float* __restrict__ in, const float* __restrict__ tg,
        float* __restrict__ out) {
    const int slice = blockIdx.x / BPS;     // (b,a)
    const int pblk  = blockIdx.x % BPS;
    const int b = slice / NA;
    const int a = slice % NA;
    const int w0 = pblk * CPB;              // window start cell

    __shared__ int           swin[CPB];
    __shared__ unsigned char ssup[CPB];
    __shared__ float         sacc[8];
    __shared__ double        dred[TPB];
    __shared__ unsigned int  s_last;

    for (int i = threadIdx.x; i < CPB; i += TPB) { swin[i] = -1; ssup[i] = 0; }
    if (threadIdx.x < 8) sacc[threadIdx.x] = 0.0f;
    __syncthreads();

    // ---- scatter this batch's 50 targets into the block's window ----
    if (threadIdx.x < NG) {
        const int g = b * NG + threadIdx.x;
        const float* t = tg + (size_t)g * 5;
        float gx = t[1] * ((float)NW / 416.0f);
        float gy = t[2] * ((float)NH / 416.0f);
        float gw = t[3] * ((float)NW / 416.0f);
        float gh = t[4] * ((float)NH / 416.0f);
        int gi = min(max((int)gx, 0), NW - 1);
        int gj = min(max((int)gy, 0), NH - 1);
        int cell = gj * NW + gi;
        if (cell >= w0 && cell < w0 + CPB) {
            int local = cell - w0;
            float area_g = (gw + 1.0f) * (gh + 1.0f);
            float best_iou = -1.0f;
            int best = 0;
            float iou_a = 0.0f;
#pragma unroll
            for (int k = 0; k < 3; k++) {
                float iw = fmaxf(fminf(gw, c_aw[k]) + 1.0f, 0.0f);
                float ih = fmaxf(fminf(gh, c_ah[k]) + 1.0f, 0.0f);
                float inter = iw * ih;
                float area_k = (c_aw[k] + 1.0f) * (c_ah[k] + 1.0f);
                float iou = inter / (area_g + area_k - inter + 1e-16f);
                if (iou > best_iou) { best_iou = iou; best = k; }  // first-max = jnp.argmax
                if (k == a) iou_a = iou;
            }
            if (iou_a > 0.5f) ssup[local] = 1;
            if (best == a) atomicMax(&swin[local], g);   // highest-g = last scatter wins
        }
    }
    __syncthreads();

    // ---- dense conf/noobj path: 4 cells per thread, float4 ----
    float sx = 0.f, sy = 0.f, sw = 0.f, sh = 0.f;
    float sconf = 0.f, snoobj = 0.f, scls = 0.f, snp = 0.f;
    const float* sbase = in + (size_t)(b * 255 + a * 85) * HW;
    const int f = (w0 >> 2) + threadIdx.x;   // float4 index within conf channel
    if (f < F4C) {
        float4 cv = reinterpret_cast<const float4*>(sbase + 4 * HW)[f];
        float cl[4] = {cv.x, cv.y, cv.z, cv.w};
        const int lbase = threadIdx.x * 4;
#pragma unroll
        for (int s = 0; s < 4; s++) {
            if (!ssup[lbase + s]) snoobj += sp(cl[s]);   // bce(conf, 0)
        }
#pragma unroll
        for (int s = 0; s < 4; s++) {
            int win = swin[lbase + s];
            if (win >= 0) {
                const int cell = w0 + lbase + s;
                const int wc = cell % NW;
                const int hc = cell / NW;
                const float* base = sbase + cell;
                const float* t = tg + (size_t)win * 5;
                float gx = t[1] * ((float)NW / 416.0f);
                float gy = t[2] * ((float)NH / 416.0f);
                float gw = t[3] * ((float)NW / 416.0f);
                float gh = t[4] * ((float)NH / 416.0f);
                float tx = gx - (float)wc;
                float ty = gy - (float)hc;
                float tw = logf(gw / c_aw[a] + 1e-16f);
                float th = logf(gh / c_ah[a] + 1e-16f);
                int clsid = min(max((int)t[0], 0), NC - 1);
                float xx = base[0];
                float xy = base[HW];
                sx += tx * sp(-xx) + (1.0f - tx) * sp(xx);
                sy += ty * sp(-xy) + (1.0f - ty) * sp(xy);
                float dw = base[2 * HW] - tw;  sw += dw * dw;
                float dh = base[3 * HW] - th;  sh += dh * dh;
                sconf += sp(-cl[s]);                     // bce(conf, 1)
#pragma unroll 8
                for (int c = 0; c < NC; c++) {
                    float xc = base[(5 + c) * HW];
                    scls += sp((c == clsid) ? -xc : xc);
                }
                snp += 1.0f;
            }
        }
    }

    // ---- block reduction (shuffle -> shared), then plain STG of partials ----
    float vals[8] = {sx, sy, sw, sh, sconf, snoobj, scls, snp};
    unsigned lane = threadIdx.x & 31;
#pragma unroll
    for (int k = 0; k < 8; k++) {
        float v = vals[k];
#pragma unroll
        for (int o = 16; o > 0; o >>= 1) v += __shfl_down_sync(0xffffffffu, v, o);
        if (lane == 0) atomicAdd(&sacc[k], v);
    }
    __syncthreads();
    if (threadIdx.x < 8) g_part[blockIdx.x * 8 + threadIdx.x] = sacc[threadIdx.x];

    // ---- last-block-done final reduction (threadFenceReduction pattern) ----
    if (threadIdx.x == 0) {
        __threadfence();
        unsigned int v = atomicAdd(&g_done, 1u);
        s_last = (v == (unsigned int)(GRID - 1)) ? 1u : 0u;
    }
    __syncthreads();
    if (s_last) {
        const int comp = threadIdx.x & 7;
        const int row  = threadIdx.x >> 3;   // 0..31
        double acc = 0.0;
        for (int i = row; i < GRID; i += 32)
            acc += (double)g_part[i * 8 + comp];
        dred[threadIdx.x] = acc;
        __syncthreads();
        if (threadIdx.x < 8) {
            double s = 0.0;
#pragma unroll
            for (int r = 0; r < 32; r++) s += dred[r * 8 + threadIdx.x];
            dred[threadIdx.x] = s;
        }
        __syncthreads();
        if (threadIdx.x == 0) {
            const double N = (double)CELLS;
            double lx = dred[0] / N;
            double ly = dred[1] / N;
            double lw = dred[2] / N;
            double lh = dred[3] / N;
            double lconf = dred[4] / N + 0.5 * (dred[5] / N);
            double denom = dred[7] * (double)NC;
            if (denom < 1.0) denom = 1.0;
            double lcls = dred[6] / denom;
            out[0] = (float)(2.5 * (lx + ly) + 2.5 * (lw + lh) + lconf + lcls);
            g_done = 0u;                      // restore pristine state for replay
            __threadfence();
        }
    }
}

extern "C" void kernel_launch(void* const* d_in, const int* in_sizes, int n_in,
                              void* d_out, int out_size) {
    const float* inp = (const float*)d_in[0];   // [32,255,52,52]
    const float* tgt = (const float*)d_in[1];   // [32,50,5]
    k_fused<<<GRID, TPB>>>(inp, tgt, (float*)d_out);
}

// round 4
// speedup vs baseline: 1.9893x; 1.4031x over previous
#include <cuda_runtime.h>
#include <math.h>

#define NB 32
#define NA 3
#define NH 52
#define NW 52
#define NG 50
#define NC 80
#define HW (NH * NW)            // 2704
#define F4C (HW / 4)            // 676
#define TPB 256
#define NWARP (TPB / 32)
#define CPB 1024                // cells per block window
#define BPS 3                   // blocks per (b,a) slice
#define GRID (NB * NA * BPS)    // 288
#define CELLS (NB * NA * HW)    // 259584
#define MAXWIN 64               // >= NG

__device__ float        g_part[GRID * 8];
__device__ unsigned int g_done;             // zero-init; last block restores zero

__constant__ float c_aw[3] = {1.25f, 2.0f, 4.125f};
__constant__ float c_ah[3] = {1.625f, 3.75f, 2.875f};

// min(softplus(x), 100) == bce(sigm(x), 0) with torch's -100 log clamp
__device__ __forceinline__ float sp(float x) {
    float r = fmaxf(x, 0.0f) + __logf(1.0f + __expf(-fabsf(x)));
    return fminf(r, 100.0f);
}

__global__ void __launch_bounds__(TPB)
k_fused(const float* __restrict__ in, const float* __restrict__ tg,
        float* __restrict__ out) {
    const int slice = blockIdx.x / BPS;
    const int pblk  = blockIdx.x % BPS;
    const int b = slice / NA;
    const int a = slice % NA;
    const int w0 = pblk * CPB;

    __shared__ int           swin[CPB];
    __shared__ unsigned char ssup[CPB];
    __shared__ float         sacc[8];
    __shared__ int           list_cell[MAXWIN];
    __shared__ int           list_g[MAXWIN];
    __shared__ int           list_n;
    __shared__ double        dred[TPB];
    __shared__ unsigned int  s_last;

    for (int i = threadIdx.x; i < CPB; i += TPB) { swin[i] = -1; ssup[i] = 0; }
    if (threadIdx.x < 8) sacc[threadIdx.x] = 0.0f;
    if (threadIdx.x == 0) list_n = 0;
    __syncthreads();

    // ---- scatter this batch's targets into the block window ----
    if (threadIdx.x < NG) {
        const int g = b * NG + threadIdx.x;
        const float* t = tg + (size_t)g * 5;
        float gx = t[1] * ((float)NW / 416.0f);
        float gy = t[2] * ((float)NH / 416.0f);
        float gw = t[3] * ((float)NW / 416.0f);
        float gh = t[4] * ((float)NH / 416.0f);
        int gi = min(max((int)gx, 0), NW - 1);
        int gj = min(max((int)gy, 0), NH - 1);
        int cell = gj * NW + gi;
        if (cell >= w0 && cell < w0 + CPB) {
            int local = cell - w0;
            float area_g = (gw + 1.0f) * (gh + 1.0f);
            float best_iou = -1.0f;
            int best = 0;
            float iou_a = 0.0f;
#pragma unroll
            for (int k = 0; k < 3; k++) {
                float iw = fmaxf(fminf(gw, c_aw[k]) + 1.0f, 0.0f);
                float ih = fmaxf(fminf(gh, c_ah[k]) + 1.0f, 0.0f);
                float inter = iw * ih;
                float area_k = (c_aw[k] + 1.0f) * (c_ah[k] + 1.0f);
                float iou = inter / (area_g + area_k - inter + 1e-16f);
                if (iou > best_iou) { best_iou = iou; best = k; }  // first-max = jnp.argmax
                if (k == a) iou_a = iou;
            }
            if (iou_a > 0.5f) ssup[local] = 1;
            if (best == a) atomicMax(&swin[local], g);   // highest-g = last scatter wins
        }
    }
    __syncthreads();

    // ---- compact winner cells into a list (each thread owns its 4 cells) ----
    {
        const int lbase = threadIdx.x * 4;
#pragma unroll
        for (int s = 0; s < 4; s++) {
            int wv = swin[lbase + s];
            if (wv >= 0) {
                int pos = atomicAdd(&list_n, 1);
                list_cell[pos] = lbase + s;   // local cell index within window
                list_g[pos] = wv;
            }
        }
    }

    // ---- dense conf/noobj path: 4 cells/thread via float4 ----
    float snoobj = 0.f;
    const float* sbase = in + (size_t)(b * 255 + a * 85) * HW;
    const int f = (w0 >> 2) + threadIdx.x;
    if (f < F4C) {
        float4 cv = reinterpret_cast<const float4*>(sbase + 4 * HW)[f];
        float cl[4] = {cv.x, cv.y, cv.z, cv.w};
        const int lbase = threadIdx.x * 4;
#pragma unroll
        for (int s = 0; s < 4; s++)
            if (!ssup[lbase + s]) snoobj += sp(cl[s]);   // bce(conf, 0)
    }
    {   // reduce noobj within warp, add to shared
        unsigned lane = threadIdx.x & 31;
        float v = snoobj;
#pragma unroll
        for (int o = 16; o > 0; o >>= 1) v += __shfl_down_sync(0xffffffffu, v, o);
        if (lane == 0) atomicAdd(&sacc[5], v);
    }
    __syncthreads();

    // ---- winner path: one warp per list entry, lanes split the 85 channels ----
    {
        const int warp = threadIdx.x >> 5;
        const int lane = threadIdx.x & 31;
        float acc_x = 0.f, acc_y = 0.f, acc_w = 0.f, acc_h = 0.f, acc_c = 0.f;
        float acc_cls = 0.f;
        const int n = list_n;
        for (int e = warp; e < n; e += NWARP) {
            const int cell = w0 + list_cell[e];
            const int win  = list_g[e];
            const float* t = tg + (size_t)win * 5;
            // every lane computes target params (cheap; t is L1/L2 hot)
            float gx = __ldg(t + 1) * ((float)NW / 416.0f);
            float gy = __ldg(t + 2) * ((float)NH / 416.0f);
            float gw = __ldg(t + 3) * ((float)NW / 416.0f);
            float gh = __ldg(t + 4) * ((float)NH / 416.0f);
            int clsid = min(max((int)__ldg(t + 0), 0), NC - 1);
            const float* base = sbase + cell;
            // lanes 0..4: box + conf terms
            if (lane < 5) {
                float xv = base[lane * HW];   // one load per lane, all concurrent
                if (lane == 0) {
                    float tx = gx - (float)(cell % NW);
                    acc_x += tx * sp(-xv) + (1.0f - tx) * sp(xv);
                } else if (lane == 1) {
                    float ty = gy - (float)(cell / NW);
                    acc_y += ty * sp(-xv) + (1.0f - ty) * sp(xv);
                } else if (lane == 2) {
                    float d = xv - logf(gw / c_aw[a] + 1e-16f);
                    acc_w += d * d;
                } else if (lane == 3) {
                    float d = xv - logf(gh / c_ah[a] + 1e-16f);
                    acc_h += d * d;
                } else {
                    acc_c += sp(-xv);         // bce(conf, 1)
                }
            }
            // classes: lane handles c = lane, lane+32, lane+64
            float x0 = base[(5 + lane) * HW];
            float x1 = base[(5 + lane + 32) * HW];
            acc_cls += sp((lane      == clsid) ? -x0 : x0);
            acc_cls += sp((lane + 32 == clsid) ? -x1 : x1);
            if (lane < 16) {
                float x2 = base[(5 + lane + 64) * HW];
                acc_cls += sp((lane + 64 == clsid) ? -x2 : x2);
            }
        }
        // reduce cls across warp; scalars live in fixed lanes
        float v = acc_cls;
#pragma unroll
        for (int o = 16; o > 0; o >>= 1) v += __shfl_down_sync(0xffffffffu, v, o);
        if (lane == 0 && v != 0.0f) atomicAdd(&sacc[6], v);
        if (acc_x != 0.f) atomicAdd(&sacc[0], acc_x);
        if (acc_y != 0.f) atomicAdd(&sacc[1], acc_y);
        if (acc_w != 0.f) atomicAdd(&sacc[2], acc_w);
        if (acc_h != 0.f) atomicAdd(&sacc[3], acc_h);
        if (acc_c != 0.f) atomicAdd(&sacc[4], acc_c);
        if (threadIdx.x == 0) sacc[7] = (float)n;
    }
    __syncthreads();

    if (threadIdx.x < 8) g_part[blockIdx.x * 8 + threadIdx.x] = sacc[threadIdx.x];

    // ---- last-block final reduction ----
    if (threadIdx.x == 0) {
        __threadfence();
        unsigned int v = atomicAdd(&g_done, 1u);
        s_last = (v == (unsigned int)(GRID - 1)) ? 1u : 0u;
    }
    __syncthreads();
    if (s_last) {
        const int comp = threadIdx.x & 7;
        const int row  = threadIdx.x >> 3;
        double acc = 0.0;
        for (int i = row; i < GRID; i += 32)
            acc += (double)g_part[i * 8 + comp];
        dred[threadIdx.x] = acc;
        __syncthreads();
        if (threadIdx.x < 8) {
            double s = 0.0;
#pragma unroll
            for (int r = 0; r < 32; r++) s += dred[r * 8 + threadIdx.x];
            dred[threadIdx.x] = s;
        }
        __syncthreads();
        if (threadIdx.x == 0) {
            const double N = (double)CELLS;
            double lx = dred[0] / N;
            double ly = dred[1] / N;
            double lw = dred[2] / N;
            double lh = dred[3] / N;
            double lconf = dred[4] / N + 0.5 * (dred[5] / N);
            double denom = dred[7] * (double)NC;
            if (denom < 1.0) denom = 1.0;
            double lcls = dred[6] / denom;
            out[0] = (float)(2.5 * (lx + ly) + 2.5 * (lw + lh) + lconf + lcls);
            g_done = 0u;
            __threadfence();
        }
    }
}

extern "C" void kernel_launch(void* const* d_in, const int* in_sizes, int n_in,
                              void* d_out, int out_size) {
    const float* inp = (const float*)d_in[0];   // [32,255,52,52]
    const float* tgt = (const float*)d_in[1];   // [32,50,5]
    k_fused<<<GRID, TPB>>>(inp, tgt, (float*)d_out);
}

// round 5
// speedup vs baseline: 2.2010x; 1.1064x over previous
#include <cuda_runtime.h>
#include <math.h>

#define NB 32
#define NA 3
#define NH 52
#define NW 52
#define NG 50
#define NC 80
#define ATTRS 85
#define HW (NH * NW)            // 2704
#define F4C (HW / 4)            // 676
#define TPB 256
#define CPB 1024                // cells per conf-block window
#define BPS 3                   // conf blocks per (b,a) slice
#define NCONF (NB * NA * BPS)   // 288
#define WPB 4                   // winner blocks per batch
#define TGT_PER_WB 13           // ceil(NG / WPB)
#define NWIN (NB * WPB)         // 128
#define GRID (NCONF + NWIN)     // 416
#define WITERS 5                // ceil(TGT_PER_WB*ATTRS / TPB) = ceil(1105/256)
#define CELLS (NB * NA * HW)    // 259584

__device__ float        g_part[GRID * 8];
__device__ unsigned int g_done;             // zero-init; last block restores zero

__constant__ float c_aw[3] = {1.25f, 2.0f, 4.125f};
__constant__ float c_ah[3] = {1.625f, 3.75f, 2.875f};

// min(softplus(x), 100) == bce(sigm(x), 0) with torch's -100 log clamp
__device__ __forceinline__ float sp(float x) {
    float r = fmaxf(x, 0.0f) + __logf(1.0f + __expf(-fabsf(x)));
    return fminf(r, 100.0f);
}

__global__ void __launch_bounds__(TPB)
k_fused(const float* __restrict__ in, const float* __restrict__ tg,
        float* __restrict__ out) {
    __shared__ float sacc[8];
    __shared__ double dred[TPB];
    __shared__ unsigned int s_last;
    if (threadIdx.x < 8) sacc[threadIdx.x] = 0.0f;

    if (blockIdx.x < NCONF) {
        // ================= CONF / NOOBJ BLOCK =================
        const int slice = blockIdx.x / BPS;
        const int pblk  = blockIdx.x % BPS;
        const int b = slice / NA;
        const int a = slice % NA;
        const int w0 = pblk * CPB;

        __shared__ unsigned char ssup[CPB];
        for (int i = threadIdx.x; i < CPB; i += TPB) ssup[i] = 0;
        __syncthreads();

        if (threadIdx.x < NG) {
            const float* t = tg + (size_t)(b * NG + threadIdx.x) * 5;
            float gx = t[1] * ((float)NW / 416.0f);
            float gy = t[2] * ((float)NH / 416.0f);
            float gw = t[3] * ((float)NW / 416.0f);
            float gh = t[4] * ((float)NH / 416.0f);
            int gi = min(max((int)gx, 0), NW - 1);
            int gj = min(max((int)gy, 0), NH - 1);
            int cell = gj * NW + gi;
            if (cell >= w0 && cell < w0 + CPB) {
                float area_g = (gw + 1.0f) * (gh + 1.0f);
                float iw = fmaxf(fminf(gw, c_aw[a]) + 1.0f, 0.0f);
                float ih = fmaxf(fminf(gh, c_ah[a]) + 1.0f, 0.0f);
                float inter = iw * ih;
                float area_a = (c_aw[a] + 1.0f) * (c_ah[a] + 1.0f);
                float iou = inter / (area_g + area_a - inter + 1e-16f);
                if (iou > 0.5f) ssup[cell - w0] = 1;
            }
        }
        __syncthreads();

        float snoobj = 0.f;
        const float* confc = in + (size_t)(b * 255 + a * ATTRS + 4) * HW;
        const int f = (w0 >> 2) + threadIdx.x;
        if (f < F4C) {
            float4 cv = reinterpret_cast<const float4*>(confc)[f];
            const int lb = threadIdx.x * 4;
            if (!ssup[lb + 0]) snoobj += sp(cv.x);
            if (!ssup[lb + 1]) snoobj += sp(cv.y);
            if (!ssup[lb + 2]) snoobj += sp(cv.z);
            if (!ssup[lb + 3]) snoobj += sp(cv.w);
        }
        unsigned lane = threadIdx.x & 31;
#pragma unroll
        for (int o = 16; o > 0; o >>= 1) snoobj += __shfl_down_sync(0xffffffffu, snoobj, o);
        if (lane == 0 && snoobj != 0.0f) atomicAdd(&sacc[5], snoobj);
    } else {
        // ================= WINNER (MASK) BLOCK =================
        const int wb  = blockIdx.x - NCONF;
        const int b   = wb / WPB;
        const int sub = wb % WPB;
        const int lo  = sub * TGT_PER_WB;
        const int hi  = min(NG, lo + TGT_PER_WB);

        __shared__ int   s_base[NG];    // channel-0 element offset in `in`
        __shared__ float s_tx[NG], s_ty[NG], s_tw[NG], s_th[NG];
        __shared__ int   s_cls[NG];
        __shared__ int   s_key[NG];     // best*HW + cell: collision key
        __shared__ unsigned char s_alive[NG];

        if (threadIdx.x < NG) {
            const int t_i = threadIdx.x;
            const float* t = tg + (size_t)(b * NG + t_i) * 5;
            float gx = t[1] * ((float)NW / 416.0f);
            float gy = t[2] * ((float)NH / 416.0f);
            float gw = t[3] * ((float)NW / 416.0f);
            float gh = t[4] * ((float)NH / 416.0f);
            int gi = min(max((int)gx, 0), NW - 1);
            int gj = min(max((int)gy, 0), NH - 1);
            int cell = gj * NW + gi;
            float area_g = (gw + 1.0f) * (gh + 1.0f);
            float best_iou = -1.0f;
            int best = 0;
#pragma unroll
            for (int k = 0; k < 3; k++) {
                float iw = fmaxf(fminf(gw, c_aw[k]) + 1.0f, 0.0f);
                float ih = fmaxf(fminf(gh, c_ah[k]) + 1.0f, 0.0f);
                float inter = iw * ih;
                float area_k = (c_aw[k] + 1.0f) * (c_ah[k] + 1.0f);
                float iou = inter / (area_g + area_k - inter + 1e-16f);
                if (iou > best_iou) { best_iou = iou; best = k; }  // first-max = jnp.argmax
            }
            s_key[t_i]  = best * HW + cell;
            s_base[t_i] = (b * 255 + best * ATTRS) * HW + cell;
            s_tx[t_i]   = gx - (float)gi;
            s_ty[t_i]   = gy - (float)gj;
            s_tw[t_i]   = logf(gw / c_aw[best] + 1e-16f);
            s_th[t_i]   = logf(gh / c_ah[best] + 1e-16f);
            s_cls[t_i]  = min(max((int)t[0], 0), NC - 1);
        }
        __syncthreads();
        if (threadIdx.x < NG) {
            unsigned char alive = 1;
            int key = s_key[threadIdx.x];
            for (int t2 = threadIdx.x + 1; t2 < NG; t2++)
                if (s_key[t2] == key) alive = 0;   // later scatter overwrites = max-g
            s_alive[threadIdx.x] = alive;
        }
        __syncthreads();

        // flat work list: (target in [lo,hi)) x (channel 0..84); front-batched loads
        const int nitems = (hi - lo) * ATTRS;
        float xv[WITERS];
        int   tgi[WITERS], chi[WITERS];
#pragma unroll
        for (int i = 0; i < WITERS; i++) {
            int w = threadIdx.x + i * TPB;
            bool valid = w < nitems;
            int tgt = lo + (valid ? w / ATTRS : 0);
            int ch  = valid ? w % ATTRS : 0;
            tgi[i] = valid ? tgt : -1;
            chi[i] = ch;
            const float* addr = in + (size_t)s_base[tgt] + (size_t)ch * HW;
            xv[i] = valid ? __ldg(addr) : 0.0f;
        }
        float ax = 0.f, ay = 0.f, aw2 = 0.f, ah2 = 0.f, ac = 0.f, acls = 0.f;
#pragma unroll
        for (int i = 0; i < WITERS; i++) {
            int tgt = tgi[i];
            if (tgt < 0 || !s_alive[tgt]) continue;
            float x = xv[i];
            int ch = chi[i];
            if (ch >= 5) {
                acls += sp((ch - 5 == s_cls[tgt]) ? -x : x);
            } else if (ch == 0) {
                float tx = s_tx[tgt];
                ax += tx * sp(-x) + (1.0f - tx) * sp(x);
            } else if (ch == 1) {
                float ty = s_ty[tgt];
                ay += ty * sp(-x) + (1.0f - ty) * sp(x);
            } else if (ch == 2) {
                float d = x - s_tw[tgt]; aw2 += d * d;
            } else if (ch == 3) {
                float d = x - s_th[tgt]; ah2 += d * d;
            } else {
                ac += sp(-x);                       // bce(conf, 1)
            }
        }
        float np = (threadIdx.x >= (unsigned)lo && threadIdx.x < (unsigned)hi &&
                    s_alive[threadIdx.x]) ? 1.0f : 0.0f;

        float vals[8] = {ax, ay, aw2, ah2, ac, 0.f, acls, np};
        unsigned lane = threadIdx.x & 31;
#pragma unroll
        for (int k = 0; k < 8; k++) {
            float v = vals[k];
#pragma unroll
            for (int o = 16; o > 0; o >>= 1) v += __shfl_down_sync(0xffffffffu, v, o);
            if (lane == 0 && v != 0.0f) atomicAdd(&sacc[k], v);
        }
    }
    __syncthreads();
    if (threadIdx.x < 8) g_part[blockIdx.x * 8 + threadIdx.x] = sacc[threadIdx.x];

    // ---- last-block final reduction ----
    if (threadIdx.x == 0) {
        __threadfence();
        unsigned int v = atomicAdd(&g_done, 1u);
        s_last = (v == (unsigned int)(GRID - 1)) ? 1u : 0u;
    }
    __syncthreads();
    if (s_last) {
        const int comp = threadIdx.x & 7;
        const int row  = threadIdx.x >> 3;
        double acc = 0.0;
        for (int i = row; i < GRID; i += 32)
            acc += (double)g_part[i * 8 + comp];
        dred[threadIdx.x] = acc;
        __syncthreads();
        if (threadIdx.x < 8) {
            double s = 0.0;
#pragma unroll
            for (int r = 0; r < 32; r++) s += dred[r * 8 + threadIdx.x];
            dred[threadIdx.x] = s;
        }
        __syncthreads();
        if (threadIdx.x == 0) {
            const double N = (double)CELLS;
            double lx = dred[0] / N;
            double ly = dred[1] / N;
            double lw = dred[2] / N;
            double lh = dred[3] / N;
            double lconf = dred[4] / N + 0.5 * (dred[5] / N);
            double denom = dred[7] * (double)NC;
            if (denom < 1.0) denom = 1.0;
            double lcls = dred[6] / denom;
            out[0] = (float)(2.5 * (lx + ly) + 2.5 * (lw + lh) + lconf + lcls);
            g_done = 0u;
            __threadfence();
        }
    }
}

extern "C" void kernel_launch(void* const* d_in, const int* in_sizes, int n_in,
                              void* d_out, int out_size) {
    const float* inp = (const float*)d_in[0];   // [32,255,52,52]
    const float* tgt = (const float*)d_in[1];   // [32,50,5]
    k_fused<<<GRID, TPB>>>(inp, tgt, (float*)d_out);
}